// round 10
// baseline (speedup 1.0000x reference)
#include <cuda_runtime.h>
#include <cuda_fp16.h>
#include <cstdint>
#include <math.h>

// ---------------- problem constants ----------------
#define TB   8
#define LT   512
#define LS   512
#define DM   512
#define NH   8
#define DK   64
#define DV   64
#define DI   2048
#define NL   6
#define TOK  (TB*LT)   // 4096
#define HB   (NH*TB)   // 64

#define EPSLN 1e-5f
#define ATT_SCALE 0.044194173824159216f   // 1/sqrt(512)

#define X_SIZE   ((size_t)TOK*DM)
#define ATT_L    ((size_t)HB*LT*LT)
#define SLF_SIZE ((size_t)NL*ATT_L)

// head-major plane: [plane][tok][64]
#define HM_Z     ((size_t)LT*DK)          // 32768
#define HM_PLANE ((size_t)TOK*64)         // 262144

// ---------------- scratch ----------------
__device__ float g_x  [TOK*DM];
__device__ float g_tmp[TOK*DM];
__device__ float g_qkv[24*TOK*64];            // self: q 0-7, k 8-15, v 16-23 (cross-Q reuses 0-7)
__device__ float g_kvc[NL*16*TOK*64];         // cross K planes 0-7, V 8-15, per layer
__device__ float g_ao [8*TOK*64];
__device__ float g_ffn[TOK*DI];

// fp16 weights, [n][k] layout
__device__ __half g_wqkvS[(size_t)NL*1536*512];
__device__ __half g_wqC  [(size_t)NL*512*512];
__device__ __half g_wkvC [(size_t)NL*1024*512];
__device__ __half g_pwH  [(size_t)2*NL*512*512];
__device__ __half g_f1H  [(size_t)NL*512*2048];
__device__ __half g_f2H  [(size_t)NL*512*2048];

// ---------------- helpers ----------------
__device__ __forceinline__ uint32_t smem_u32(const void* p) {
    uint32_t a;
    asm("{ .reg .u64 t; cvta.to.shared.u64 t, %1; cvt.u32.u64 %0, t; }" : "=r"(a) : "l"(p));
    return a;
}

#define LDSM4(r, addr) \
    asm volatile("ldmatrix.sync.aligned.m8n8.x4.shared.b16 {%0,%1,%2,%3}, [%4];" \
        : "=r"((r)[0]), "=r"((r)[1]), "=r"((r)[2]), "=r"((r)[3]) : "r"(addr))

__device__ __forceinline__ void mma_f16(float* d, const unsigned* a, unsigned b0, unsigned b1)
{
    asm volatile("mma.sync.aligned.m16n8k16.row.col.f32.f16.f16.f32 "
        "{%0,%1,%2,%3}, {%4,%5,%6,%7}, {%8,%9}, {%0,%1,%2,%3};\n"
        : "+f"(d[0]), "+f"(d[1]), "+f"(d[2]), "+f"(d[3])
        : "r"(a[0]), "r"(a[1]), "r"(a[2]), "r"(a[3]), "r"(b0), "r"(b1));
}

__device__ __forceinline__ unsigned packh2(float e, float o)
{
    __half2 h = __floats2half2_rn(e, o);
    return *(unsigned*)&h;
}

// ---------------- embedding ----------------
__global__ void embed_kernel(const int* __restrict__ seq, const int* __restrict__ pos,
                             const float* __restrict__ emb, const float* __restrict__ pemb,
                             float* __restrict__ x)
{
    int i = blockIdx.x * 256 + threadIdx.x;
    int t = i / DM, d = i % DM;
    x[i] = emb[(size_t)seq[t]*DM + d] + pemb[(size_t)pos[t]*DM + d];
}

// ---------------- transpose + fp16 convert: in[b][R][C] -> out[n=(h*C+c)][R] ----------------
__global__ void transconv2_kernel(const float* __restrict__ in, __half* __restrict__ outp,
                                  int R, int C, int nhb, size_t lplane, size_t nbase)
{
    __shared__ float t[32][33];
    int bidz = blockIdx.z;
    int l = bidz / nhb, h = bidz % nhb;
    int r0 = blockIdx.x * 32, c0 = blockIdx.y * 32;
    const float* ib = in + (size_t)bidz * R * C;
#pragma unroll
    for (int i = threadIdx.y; i < 32; i += 8)
        t[i][threadIdx.x] = ib[(size_t)(r0 + i) * C + c0 + threadIdx.x];
    __syncthreads();
    __half* ob = outp + (size_t)l * lplane + nbase;
#pragma unroll
    for (int i = threadIdx.y; i < 32; i += 8)
        ob[(size_t)(h * C + c0 + i) * R + r0 + threadIdx.x] = __float2half(t[threadIdx.x][i]);
}

// ---------------- fp16 tensor-core GEMM (proven in R8) ----------------
#define AST 20
template<bool BIAS, bool RES, bool RELU, bool AHEAD, bool CHEAD>
__global__ void __launch_bounds__(256) hgemm_kernel(
    const float* __restrict__ A, const __half* __restrict__ Bw,
    const float* __restrict__ bias, const float* __restrict__ res,
    float* __restrict__ C, int K, int lda, int ldc, size_t sB, size_t sC)
{
    __shared__ unsigned As[2][128*AST];
    __shared__ unsigned Bs[2][128*AST];
    const int tid = threadIdx.x, lane = tid & 31, wid = tid >> 5;
    const int g = lane >> 2, tg = lane & 3;
    const int bm = blockIdx.x * 128, bn = blockIdx.y * 128;
    const int z = blockIdx.z;
    const __half* Bz = Bw + (size_t)z * sB;
    float* Cz = C + (size_t)z * sC;
    const int KT = K >> 5;
    const int wm = (wid & 3) * 32, wn = (wid >> 2) * 64;

    const int r = tid >> 1, pp = tid & 1;
    float4 pa[4];
    uint4 pb[2];

    auto loadAB = [&](int kt) {
        const float* asrc = AHEAD
            ? A + (size_t)(kt >> 1) * lda + (size_t)(bm + r) * 64 + (kt & 1) * 32 + pp * 16
            : A + (size_t)(bm + r) * lda + kt * 32 + pp * 16;
        pa[0] = ((const float4*)asrc)[0];
        pa[1] = ((const float4*)asrc)[1];
        pa[2] = ((const float4*)asrc)[2];
        pa[3] = ((const float4*)asrc)[3];
        const uint4* bsrc = (const uint4*)(Bz + (size_t)(bn + r) * K + kt * 32 + pp * 16);
        pb[0] = bsrc[0];
        pb[1] = bsrc[1];
    };
    auto storeAB = [&](int buf) {
        unsigned u[8];
#pragma unroll
        for (int i = 0; i < 4; i++) {
            u[2*i]   = packh2(pa[i].x, pa[i].y);
            u[2*i+1] = packh2(pa[i].z, pa[i].w);
        }
        *(uint4*)&As[buf][r*AST + pp*8]     = make_uint4(u[0], u[1], u[2], u[3]);
        *(uint4*)&As[buf][r*AST + pp*8 + 4] = make_uint4(u[4], u[5], u[6], u[7]);
        *(uint4*)&Bs[buf][r*AST + pp*8]     = pb[0];
        *(uint4*)&Bs[buf][r*AST + pp*8 + 4] = pb[1];
    };

    float acc[2][8][4] = {};

    loadAB(0); storeAB(0); __syncthreads();

    const uint32_t aBase = smem_u32(&As[0][0]);
    const uint32_t bBase = smem_u32(&Bs[0][0]);
    const int frA  = (wm + (lane & 15)) * AST + (lane >> 4) * 4;
    const int frB  = (wn + (lane & 15)) * AST + (lane >> 4) * 4;

    for (int kt = 0; kt < KT; kt++) {
        int buf = kt & 1;
        if (kt + 1 < KT) loadAB(kt + 1);
        uint32_t aT = aBase + buf * (128*AST*4);
        uint32_t bT = bBase + buf * (128*AST*4);
#pragma unroll
        for (int ks = 0; ks < 2; ks++) {
            int k0 = ks * 8;
            unsigned a0[4], a1[4], bb[8][2];
            LDSM4(a0, aT + (frA + k0) * 4);
            LDSM4(a1, aT + (frA + 16*AST + k0) * 4);
#pragma unroll
            for (int nj = 0; nj < 4; nj++) {
                unsigned t4[4];
                LDSM4(t4, bT + (frB + nj*16*AST + k0) * 4);
                bb[2*nj][0]   = t4[0]; bb[2*nj+1][0] = t4[1];
                bb[2*nj][1]   = t4[2]; bb[2*nj+1][1] = t4[3];
            }
#pragma unroll
            for (int ni = 0; ni < 8; ni++) {
                mma_f16(acc[0][ni], a0, bb[ni][0], bb[ni][1]);
                mma_f16(acc[1][ni], a1, bb[ni][0], bb[ni][1]);
            }
        }
        if (kt + 1 < KT) storeAB((kt + 1) & 1);
        __syncthreads();
    }

#pragma unroll
    for (int mi = 0; mi < 2; mi++) {
        int rr = bm + wm + mi*16 + g;
#pragma unroll
        for (int ni = 0; ni < 8; ni++) {
            int c = bn + wn + ni*8 + 2*tg;
            float2 v0 = make_float2(acc[mi][ni][0], acc[mi][ni][1]);
            float2 v1 = make_float2(acc[mi][ni][2], acc[mi][ni][3]);
            if (BIAS) {
                float2 bv = *(const float2*)(bias + c);
                v0.x += bv.x; v0.y += bv.y; v1.x += bv.x; v1.y += bv.y;
            }
            if (RES) {
                float2 r0v = *(const float2*)(res + (size_t)rr*ldc + c);
                float2 r1v = *(const float2*)(res + (size_t)(rr+8)*ldc + c);
                v0.x += r0v.x; v0.y += r0v.y; v1.x += r1v.x; v1.y += r1v.y;
            }
            if (RELU) {
                v0.x = fmaxf(v0.x, 0.f); v0.y = fmaxf(v0.y, 0.f);
                v1.x = fmaxf(v1.x, 0.f); v1.y = fmaxf(v1.y, 0.f);
            }
            if (CHEAD) {
                int plane = c >> 6, e = c & 63;
                float* cp = Cz + (size_t)plane * HM_PLANE + (size_t)rr * 64 + e;
                *(float2*)cp = v0;
                *(float2*)(cp + 8*64) = v1;
            } else {
                float* cp = Cz + (size_t)rr * ldc + c;
                *(float2*)cp = v0;
                *(float2*)(cp + (size_t)8*ldc) = v1;
            }
        }
    }
}

// ---------------- fused attention: scores + masked softmax + P write + P@V ----------------
// grid (16,1,HB), 256 thr. Per block: 32 q-rows x full 512 s. Scores stay in regs.
#define QS_U  (32*36)
#define KS_U  (128*36)
#define PS_U  (32*260)
#define VS_U  (64*68)
#define ATT_SMEM ((QS_U + KS_U + PS_U + VS_U + 512 + 256) * 4)

template<bool SELF>
__global__ void __launch_bounds__(256) attn_kernel(
    const float* __restrict__ Qroot, const float* __restrict__ Kroot,
    const float* __restrict__ Vroot, const int* __restrict__ seq,
    float* __restrict__ Pout, float* __restrict__ ao)
{
    extern __shared__ unsigned dsm[];
    unsigned* Qs = dsm;
    unsigned* Ks = Qs + QS_U;
    unsigned* Ps = Ks + KS_U;
    unsigned* Vs = Ps + PS_U;
    float* maskv = (float*)(Vs + VS_U);
    float* red   = maskv + 512;

    const int tid = threadIdx.x, lane = tid & 31, wid = tid >> 5;
    const int g = lane >> 2, tg = lane & 3;
    const int wm = (wid & 1) * 16;        // 2 m-warp groups
    const int wn = (wid >> 1) * 32;       // 4 n-warp groups (score, chunk-local)
    const int wnV = (wid >> 1) * 16;      // 4 n-warp groups (PV)
    const int q0 = blockIdx.x * 32;
    const int z = blockIdx.z, h = z >> 3, b = z & 7;

    const float* Qb = Qroot + (size_t)h * HM_PLANE + (size_t)b * HM_Z + (size_t)q0 * DK;
    const float* Kb = Kroot + (size_t)h * HM_PLANE + (size_t)b * HM_Z;
    const float* Vb = Vroot + (size_t)h * HM_PLANE + (size_t)b * HM_Z;

    // load Q tile (32 rows x 64 cols): each of 64 threads packs 32 floats -> 16 uints
    if (tid < 64) {
        int r = tid >> 1, part = tid & 1;
        const float* src = Qb + (size_t)r * DK + part * 32;
        unsigned u[16];
#pragma unroll
        for (int i = 0; i < 8; i++) {
            float4 f = ((const float4*)src)[i];
            u[2*i]   = packh2(f.x, f.y);
            u[2*i+1] = packh2(f.z, f.w);
        }
        int o = r*36 + part*16;
#pragma unroll
        for (int qq = 0; qq < 4; qq++)
            *(uint4*)&Qs[o + 4*qq] = make_uint4(u[4*qq], u[4*qq+1], u[4*qq+2], u[4*qq+3]);
    }
    maskv[tid]       = (seq[b*LT + tid] == 0)       ? -INFINITY : 0.f;
    maskv[tid + 256] = (seq[b*LT + tid + 256] == 0) ? -INFINITY : 0.f;
    __syncthreads();

    const uint32_t qB = smem_u32(Qs);
    const uint32_t kB = smem_u32(Ks);
    const uint32_t pB = smem_u32(Ps);
    const uint32_t vB = smem_u32(Vs);

    const int ncomp = SELF ? ((blockIdx.x >> 2) + 1) : 4;

    float accS[4][4][4] = {};
    {
        const int frA = (wm + (lane & 15)) * 36 + (lane >> 4) * 4;
        const int frB = (wn + (lane & 15)) * 36 + (lane >> 4) * 4;
        for (int c = 0; c < ncomp; c++) {
            // load K chunk (128 rows x 64 cols): 256 threads, 32 floats -> 16 uints each
            {
                int r = tid >> 1, part = tid & 1;
                const float* src = Kb + (size_t)(c*128 + r) * DK + part * 32;
                unsigned u[16];
#pragma unroll
                for (int i = 0; i < 8; i++) {
                    float4 f = ((const float4*)src)[i];
                    u[2*i]   = packh2(f.x, f.y);
                    u[2*i+1] = packh2(f.z, f.w);
                }
                int o = r*36 + part*16;
#pragma unroll
                for (int qq = 0; qq < 4; qq++)
                    *(uint4*)&Ks[o + 4*qq] = make_uint4(u[4*qq], u[4*qq+1], u[4*qq+2], u[4*qq+3]);
            }
            __syncthreads();
#pragma unroll
            for (int ks = 0; ks < 4; ks++) {
                int k0 = ks * 8;
                unsigned a0[4], bb[4][2];
                LDSM4(a0, qB + (frA + k0) * 4);
#pragma unroll
                for (int nj = 0; nj < 2; nj++) {
                    unsigned t4[4];
                    LDSM4(t4, kB + (frB + nj*16*36 + k0) * 4);
                    bb[2*nj][0] = t4[0]; bb[2*nj+1][0] = t4[1];
                    bb[2*nj][1] = t4[2]; bb[2*nj+1][1] = t4[3];
                }
#pragma unroll
                for (int ni = 0; ni < 4; ni++)
                    mma_f16(accS[c][ni], a0, bb[ni][0], bb[ni][1]);
            }
            __syncthreads();
        }
    }

    // ---- masked softmax over registers ----
    const int row0 = q0 + wm + g;
    const int r0l = wm + g, r1l = wm + g + 8;
    float m0 = -INFINITY, m1 = -INFINITY;
#pragma unroll
    for (int c = 0; c < 4; c++)
#pragma unroll
        for (int ni = 0; ni < 4; ni++) {
            int col = c*128 + wn + ni*8 + tg*2;
            float* a = accS[c][ni];
            float mv0 = maskv[col], mv1 = maskv[col+1];
            a[0] = a[0]*ATT_SCALE + mv0;
            a[1] = a[1]*ATT_SCALE + mv1;
            a[2] = a[2]*ATT_SCALE + mv0;
            a[3] = a[3]*ATT_SCALE + mv1;
            if (SELF) {
                if (col     > row0)   a[0] = -INFINITY;
                if (col + 1 > row0)   a[1] = -INFINITY;
                if (col     > row0+8) a[2] = -INFINITY;
                if (col + 1 > row0+8) a[3] = -INFINITY;
            }
            m0 = fmaxf(m0, fmaxf(a[0], a[1]));
            m1 = fmaxf(m1, fmaxf(a[2], a[3]));
        }
    m0 = fmaxf(m0, __shfl_xor_sync(0xffffffffu, m0, 1));
    m0 = fmaxf(m0, __shfl_xor_sync(0xffffffffu, m0, 2));
    m1 = fmaxf(m1, __shfl_xor_sync(0xffffffffu, m1, 1));
    m1 = fmaxf(m1, __shfl_xor_sync(0xffffffffu, m1, 2));
    int wnidx = wid >> 1;
    if (tg == 0) { red[r0l*4 + wnidx] = m0; red[r1l*4 + wnidx] = m1; }
    __syncthreads();
    m0 = fmaxf(fmaxf(red[r0l*4], red[r0l*4+1]), fmaxf(red[r0l*4+2], red[r0l*4+3]));
    m1 = fmaxf(fmaxf(red[r1l*4], red[r1l*4+1]), fmaxf(red[r1l*4+2], red[r1l*4+3]));

    float s0 = 0.f, s1 = 0.f;
#pragma unroll
    for (int c = 0; c < 4; c++)
#pragma unroll
        for (int ni = 0; ni < 4; ni++) {
            float* a = accS[c][ni];
            a[0] = __expf(a[0] - m0); a[1] = __expf(a[1] - m0);
            a[2] = __expf(a[2] - m1); a[3] = __expf(a[3] - m1);
            s0 += a[0] + a[1];
            s1 += a[2] + a[3];
        }
    s0 += __shfl_xor_sync(0xffffffffu, s0, 1);
    s0 += __shfl_xor_sync(0xffffffffu, s0, 2);
    s1 += __shfl_xor_sync(0xffffffffu, s1, 1);
    s1 += __shfl_xor_sync(0xffffffffu, s1, 2);
    if (tg == 0) { red[128 + r0l*4 + wnidx] = s0; red[128 + r1l*4 + wnidx] = s1; }
    __syncthreads();
    s0 = red[128+r0l*4] + red[128+r0l*4+1] + red[128+r0l*4+2] + red[128+r0l*4+3];
    s1 = red[128+r1l*4] + red[128+r1l*4+1] + red[128+r1l*4+2] + red[128+r1l*4+3];
    float inv0 = 1.f / s0, inv1 = 1.f / s1;

    // ---- write P (fp32 -> d_out) + stash fp16 into Ps ----
    float* Prow0 = Pout + (size_t)z * LT * LT + (size_t)row0 * LT;
    float* Prow1 = Prow0 + 8 * LT;
#pragma unroll
    for (int c = 0; c < 4; c++)
#pragma unroll
        for (int ni = 0; ni < 4; ni++) {
            int col = c*128 + wn + ni*8 + tg*2;
            float* a = accS[c][ni];
            float p00 = a[0]*inv0, p01 = a[1]*inv0;
            float p10 = a[2]*inv1, p11 = a[3]*inv1;
            *(float2*)(Prow0 + col) = make_float2(p00, p01);
            *(float2*)(Prow1 + col) = make_float2(p10, p11);
            Ps[r0l*260 + (col>>1)] = packh2(p00, p01);
            Ps[r1l*260 + (col>>1)] = packh2(p10, p11);
        }
    __syncthreads();

    // ---- P @ V ----
    float accV[2][4] = {};
    {
        const int frB = (wnV + (lane & 15)) * 68 + (lane >> 4) * 4;
        for (int c = 0; c < ncomp; c++) {
            // load V chunk (128 s x 64 e) transposed -> Vs[e][s-pairs]
            {
                int e = tid & 63, sg = tid >> 6;
                unsigned u[16];
#pragma unroll
                for (int j = 0; j < 16; j++) {
                    float v0 = Vb[(size_t)(c*128 + sg*32 + 2*j)   * 64 + e];
                    float v1 = Vb[(size_t)(c*128 + sg*32 + 2*j+1) * 64 + e];
                    u[j] = packh2(v0, v1);
                }
#pragma unroll
                for (int qq = 0; qq < 4; qq++)
                    *(uint4*)&Vs[e*68 + sg*16 + qq*4] =
                        make_uint4(u[4*qq], u[4*qq+1], u[4*qq+2], u[4*qq+3]);
            }
            __syncthreads();
            const int frA = (wm + (lane & 15)) * 260 + (lane >> 4) * 4 + c*64;
#pragma unroll
            for (int ks = 0; ks < 8; ks++) {
                int k0 = ks * 8;
                unsigned a0[4], t4[4];
                LDSM4(a0, pB + (frA + k0) * 4);
                LDSM4(t4, vB + (frB + k0) * 4);
                mma_f16(accV[0], a0, t4[0], t4[2]);
                mma_f16(accV[1], a0, t4[1], t4[3]);
            }
            __syncthreads();
        }
    }

    float* aoh = ao + (size_t)h * HM_PLANE;
    size_t tok0 = (size_t)b * LT + row0;
#pragma unroll
    for (int ni = 0; ni < 2; ni++) {
        int e = wnV + ni*8 + tg*2;
        *(float2*)(aoh + tok0*64 + e)     = make_float2(accV[ni][0], accV[ni][1]);
        *(float2*)(aoh + (tok0+8)*64 + e) = make_float2(accV[ni][2], accV[ni][3]);
    }
}

// ---------------- LayerNorm ----------------
__global__ void ln_kernel(const float* __restrict__ in, const float* __restrict__ g,
                          const float* __restrict__ bb, float* __restrict__ out)
{
    __shared__ float sh[4];
    int row = blockIdx.x;
    int tid = threadIdx.x;
    const float* r = in + (size_t)row*DM;
    float v[4];
    float s = 0.f;
#pragma unroll
    for (int i = 0; i < 4; i++) { v[i] = r[tid + i*128]; s += v[i]; }
#pragma unroll
    for (int o = 16; o > 0; o >>= 1) s += __shfl_xor_sync(0xffffffffu, s, o);
    if ((tid & 31) == 0) sh[tid >> 5] = s;
    __syncthreads();
    s = sh[0] + sh[1] + sh[2] + sh[3];
    float mu = s * (1.f / DM);
    float s2 = 0.f;
#pragma unroll
    for (int i = 0; i < 4; i++) { float d = v[i] - mu; s2 += d*d; }
#pragma unroll
    for (int o = 16; o > 0; o >>= 1) s2 += __shfl_xor_sync(0xffffffffu, s2, o);
    __syncthreads();
    if ((tid & 31) == 0) sh[tid >> 5] = s2;
    __syncthreads();
    s2 = sh[0] + sh[1] + sh[2] + sh[3];
    float inv = rsqrtf(s2 * (1.f / DM) + EPSLN);
#pragma unroll
    for (int i = 0; i < 4; i++) {
        int d = tid + i*128;
        out[(size_t)row*DM + d] = (v[i] - mu) * inv * g[d] + bb[d];
    }
}

// ---------------- host orchestration ----------------
extern "C" void kernel_launch(void* const* d_in, const int* in_sizes, int n_in,
                              void* d_out, int out_size)
{
    (void)in_sizes; (void)n_in; (void)out_size;
    const int*   tgt_seq = (const int*)  d_in[0];
    const int*   tgt_pos = (const int*)  d_in[1];
    const int*   src_seq = (const int*)  d_in[2];
    const float* enc_out = (const float*)d_in[3];
    const float* tgt_emb = (const float*)d_in[4];
    const float* pos_emb = (const float*)d_in[5];
    const float* slf_wq  = (const float*)d_in[6];
    const float* slf_wk  = (const float*)d_in[7];
    const float* slf_wv  = (const float*)d_in[8];
    const float* slf_pw  = (const float*)d_in[9];
    const float* slf_pb  = (const float*)d_in[10];
    const float* slf_g   = (const float*)d_in[11];
    const float* slf_b   = (const float*)d_in[12];
    const float* enc_wq  = (const float*)d_in[13];
    const float* enc_wk  = (const float*)d_in[14];
    const float* enc_wv  = (const float*)d_in[15];
    const float* enc_pw  = (const float*)d_in[16];
    const float* enc_pb  = (const float*)d_in[17];
    const float* enc_g   = (const float*)d_in[18];
    const float* enc_b   = (const float*)d_in[19];
    const float* ffn_w1  = (const float*)d_in[20];
    const float* ffn_b1  = (const float*)d_in[21];
    const float* ffn_w2  = (const float*)d_in[22];
    const float* ffn_b2  = (const float*)d_in[23];
    const float* ffn_g   = (const float*)d_in[24];
    const float* ffn_b   = (const float*)d_in[25];
    float* out = (float*)d_out;

    float *x, *tmp, *qkv, *kvc, *ao, *ffnb;
    __half *wqkvS, *wqC, *wkvC, *pwH, *f1H, *f2H;
    cudaGetSymbolAddress((void**)&x,     g_x);
    cudaGetSymbolAddress((void**)&tmp,   g_tmp);
    cudaGetSymbolAddress((void**)&qkv,   g_qkv);
    cudaGetSymbolAddress((void**)&kvc,   g_kvc);
    cudaGetSymbolAddress((void**)&ao,    g_ao);
    cudaGetSymbolAddress((void**)&ffnb,  g_ffn);
    cudaGetSymbolAddress((void**)&wqkvS, g_wqkvS);
    cudaGetSymbolAddress((void**)&wqC,   g_wqC);
    cudaGetSymbolAddress((void**)&wkvC,  g_wkvC);
    cudaGetSymbolAddress((void**)&pwH,   g_pwH);
    cudaGetSymbolAddress((void**)&f1H,   g_f1H);
    cudaGetSymbolAddress((void**)&f2H,   g_f2H);

    auto hProj = hgemm_kernel<false,false,false,false,true >;
    auto hOut  = hgemm_kernel<true, true, false,true, false>;
    auto hF1   = hgemm_kernel<true, false,true, false,false>;
    auto hF2   = hgemm_kernel<true, true, false,false,false>;
    auto aSelf = attn_kernel<true>;
    auto aCross= attn_kernel<false>;

    cudaFuncSetAttribute(aSelf,  cudaFuncAttributeMaxDynamicSharedMemorySize, ATT_SMEM);
    cudaFuncSetAttribute(aCross, cudaFuncAttributeMaxDynamicSharedMemorySize, ATT_SMEM);

    dim3 tcb(32, 8);
    transconv2_kernel<<<dim3(16,2,48), tcb>>>(slf_wq, wqkvS, 512, 64, 8, (size_t)1536*512, (size_t)0*512*512);
    transconv2_kernel<<<dim3(16,2,48), tcb>>>(slf_wk, wqkvS, 512, 64, 8, (size_t)1536*512, (size_t)1*512*512);
    transconv2_kernel<<<dim3(16,2,48), tcb>>>(slf_wv, wqkvS, 512, 64, 8, (size_t)1536*512, (size_t)2*512*512);
    transconv2_kernel<<<dim3(16,2,48), tcb>>>(enc_wq, wqC,   512, 64, 8, (size_t)512*512,  0);
    transconv2_kernel<<<dim3(16,2,48), tcb>>>(enc_wk, wkvC,  512, 64, 8, (size_t)1024*512, 0);
    transconv2_kernel<<<dim3(16,2,48), tcb>>>(enc_wv, wkvC,  512, 64, 8, (size_t)1024*512, (size_t)512*512);
    transconv2_kernel<<<dim3(16,16,6), tcb>>>(slf_pw, pwH,                      512, 512, 1, (size_t)512*512, 0);
    transconv2_kernel<<<dim3(16,16,6), tcb>>>(enc_pw, pwH + (size_t)NL*512*512, 512, 512, 1, (size_t)512*512, 0);
    transconv2_kernel<<<dim3(16,64,6), tcb>>>(ffn_w1, f1H, 512, 2048, 1, (size_t)512*2048, 0);
    transconv2_kernel<<<dim3(64,16,6), tcb>>>(ffn_w2, f2H, 2048, 512, 1, (size_t)512*2048, 0);

    embed_kernel<<<(TOK*DM)/256, 256>>>(tgt_seq, tgt_pos, tgt_emb, pos_emb, x);

    // all layers' cross K/V at once
    hProj<<<dim3(32,8,6),256>>>(enc_out, wkvC, nullptr, nullptr, kvc,
                                512, 512, 0, (size_t)1024*512, (size_t)16*HM_PLANE);

    dim3 gAtt(16, 1, HB);

    for (int l = 0; l < NL; l++) {
        size_t ld = (size_t)l * DM;
        const float* kvl = kvc + (size_t)l * 16 * HM_PLANE;

        // ---- self attention ----
        hProj<<<dim3(32,12),256>>>(x, wqkvS + (size_t)l*1536*512, nullptr, nullptr, qkv,
                                   512, 512, 0, 0, 0);
        float* slfA = out + X_SIZE + (size_t)l * ATT_L;
        aSelf<<<gAtt,256,ATT_SMEM>>>(qkv, qkv + 8*HM_PLANE, qkv + 16*HM_PLANE,
                                     tgt_seq, slfA, ao);
        hOut<<<dim3(32,4),256>>>(ao, pwH + (size_t)l*512*512, slf_pb + ld, x, tmp,
                                 512, HM_PLANE, 512, 0, 0);
        ln_kernel<<<TOK,128>>>(tmp, slf_g + ld, slf_b + ld, x);

        // ---- cross attention ----
        hProj<<<dim3(32,4),256>>>(x, wqC + (size_t)l*512*512, nullptr, nullptr, qkv,
                                  512, 512, 0, 0, 0);
        float* encA = out + X_SIZE + SLF_SIZE + (size_t)l * ATT_L;
        aCross<<<gAtt,256,ATT_SMEM>>>(qkv, kvl, kvl + 8*HM_PLANE,
                                      src_seq, encA, ao);
        hOut<<<dim3(32,4),256>>>(ao, pwH + (size_t)(NL + l)*512*512, enc_pb + ld, x, tmp,
                                 512, HM_PLANE, 512, 0, 0);
        ln_kernel<<<TOK,128>>>(tmp, enc_g + ld, enc_b + ld, x);

        // ---- FFN ----
        hF1<<<dim3(32,16),256>>>(x, f1H + (size_t)l*512*2048, ffn_b1 + (size_t)l*DI, nullptr,
                                 ffnb, 512, 512, DI, 0, 0);
        hF2<<<dim3(32,4),256>>>(ffnb, f2H + (size_t)l*512*2048, ffn_b2 + ld, x, tmp,
                                2048, DI, 512, 0, 0);
        ln_kernel<<<TOK,128>>>(tmp, ffn_g + ld, ffn_b + ld, x);
    }

    cudaMemcpyAsync(out, x, X_SIZE * sizeof(float), cudaMemcpyDeviceToDevice);
}

// round 11
// speedup vs baseline: 1.1715x; 1.1715x over previous
#include <cuda_runtime.h>
#include <cuda_fp16.h>
#include <cstdint>
#include <math.h>

// ---------------- problem constants ----------------
#define TB   8
#define LT   512
#define LS   512
#define DM   512
#define NH   8
#define DK   64
#define DV   64
#define DI   2048
#define NL   6
#define TOK  (TB*LT)   // 4096
#define HB   (NH*TB)   // 64

#define EPSLN 1e-5f
#define ATT_SCALE 0.044194173824159216f   // 1/sqrt(512)

#define X_SIZE   ((size_t)TOK*DM)
#define ATT_L    ((size_t)HB*LT*LT)
#define SLF_SIZE ((size_t)NL*ATT_L)

// head-major plane: [plane][tok][64]
#define HM_Z     ((size_t)LT*DK)          // 32768
#define HM_PLANE ((size_t)TOK*64)         // 262144

// ---------------- scratch ----------------
__device__ float  g_x   [TOK*DM];
__device__ __half g_x16 [TOK*DM];
__device__ __half g_e16 [TOK*DM];
__device__ float  g_tmp [TOK*DM];
__device__ __half g_qkv [24*TOK*64];           // self: q 0-7, k 8-15, v 16-23 (cross-Q reuses 0-7)
__device__ __half g_kvc [NL*16*TOK*64];        // cross K planes 0-7, V 8-15, per layer
__device__ __half g_ao  [8*TOK*64];
__device__ __half g_ffn [TOK*DI];
__device__ __half g_p16 [HB*LT*LT];            // fp16 mirror of current attention matrix

// fp16 weights, [n][k] layout
__device__ __half g_wqkvS[(size_t)NL*1536*512];
__device__ __half g_wqC  [(size_t)NL*512*512];
__device__ __half g_wkvC [(size_t)NL*1024*512];
__device__ __half g_pwH  [(size_t)2*NL*512*512];
__device__ __half g_f1H  [(size_t)NL*512*2048];
__device__ __half g_f2H  [(size_t)NL*512*2048];

// ---------------- helpers ----------------
__device__ __forceinline__ uint32_t smem_u32(const void* p) {
    uint32_t a;
    asm("{ .reg .u64 t; cvta.to.shared.u64 t, %1; cvt.u32.u64 %0, t; }" : "=r"(a) : "l"(p));
    return a;
}

#define LDSM4(r, addr) \
    asm volatile("ldmatrix.sync.aligned.m8n8.x4.shared.b16 {%0,%1,%2,%3}, [%4];" \
        : "=r"((r)[0]), "=r"((r)[1]), "=r"((r)[2]), "=r"((r)[3]) : "r"(addr))

__device__ __forceinline__ void mma_f16(float* d, const unsigned* a, unsigned b0, unsigned b1)
{
    asm volatile("mma.sync.aligned.m16n8k16.row.col.f32.f16.f16.f32 "
        "{%0,%1,%2,%3}, {%4,%5,%6,%7}, {%8,%9}, {%0,%1,%2,%3};\n"
        : "+f"(d[0]), "+f"(d[1]), "+f"(d[2]), "+f"(d[3])
        : "r"(a[0]), "r"(a[1]), "r"(a[2]), "r"(a[3]), "r"(b0), "r"(b1));
}

__device__ __forceinline__ unsigned packh2(float e, float o)
{
    __half2 h = __floats2half2_rn(e, o);
    return *(unsigned*)&h;
}
__device__ __forceinline__ unsigned packhh(__half e, __half o)
{
    __half2 h = __halves2half2(e, o);
    return *(unsigned*)&h;
}

// ---------------- embedding (fp32 + fp16 mirror) ----------------
__global__ void embed_kernel(const int* __restrict__ seq, const int* __restrict__ pos,
                             const float* __restrict__ emb, const float* __restrict__ pemb,
                             float* __restrict__ x, __half* __restrict__ x16)
{
    int i = blockIdx.x * 256 + threadIdx.x;
    int t = i / DM, d = i % DM;
    float v = emb[(size_t)seq[t]*DM + d] + pemb[(size_t)pos[t]*DM + d];
    x[i] = v;
    x16[i] = __float2half(v);
}

// ---------------- fp32 -> fp16 convert ----------------
__global__ void f2h_kernel(const float* __restrict__ in, __half* __restrict__ o)
{
    int i = blockIdx.x * 256 + threadIdx.x;
    o[i] = __float2half(in[i]);
}

// ---------------- transpose + fp16 convert: in[b][R][C] -> out[n=(h*C+c)][R] ----------------
__global__ void transconv2_kernel(const float* __restrict__ in, __half* __restrict__ outp,
                                  int R, int C, int nhb, size_t lplane, size_t nbase)
{
    __shared__ float t[32][33];
    int bidz = blockIdx.z;
    int l = bidz / nhb, h = bidz % nhb;
    int r0 = blockIdx.x * 32, c0 = blockIdx.y * 32;
    const float* ib = in + (size_t)bidz * R * C;
#pragma unroll
    for (int i = threadIdx.y; i < 32; i += 8)
        t[i][threadIdx.x] = ib[(size_t)(r0 + i) * C + c0 + threadIdx.x];
    __syncthreads();
    __half* ob = outp + (size_t)l * lplane + nbase;
#pragma unroll
    for (int i = threadIdx.y; i < 32; i += 8)
        ob[(size_t)(h * C + c0 + i) * R + r0 + threadIdx.x] = __float2half(t[threadIdx.x][i]);
}

// merged qkv-type transpose: six [NL*8][512][64] tensors in one launch
struct TCArgs {
    const float* src[6];
    __half*      dst[6];     // already offset by nbase
};
__global__ void transconvQKV_kernel(TCArgs a)
{
    const size_t lp[6] = {(size_t)1536*512, (size_t)1536*512, (size_t)1536*512,
                          (size_t)512*512,  (size_t)1024*512, (size_t)1024*512};
    __shared__ float t[32][33];
    int zi = blockIdx.z;
    int w = zi / 48, bz = zi % 48;
    int l = bz / 8, h = bz % 8;
    int r0 = blockIdx.x * 32, c0 = blockIdx.y * 32;
    const float* ib = a.src[w] + (size_t)bz * 512 * 64;
#pragma unroll
    for (int i = threadIdx.y; i < 32; i += 8)
        t[i][threadIdx.x] = ib[(size_t)(r0 + i) * 64 + c0 + threadIdx.x];
    __syncthreads();
    __half* ob = a.dst[w] + (size_t)l * lp[w];
#pragma unroll
    for (int i = threadIdx.y; i < 32; i += 8)
        ob[(size_t)(h * 64 + c0 + i) * 512 + r0 + threadIdx.x] = __float2half(t[threadIdx.x][i]);
}

// ---------------- fp16 tensor-core GEMM: C[M,N] = A[M,K] @ B ----------------
// A fp16 (straight copy to smem), B fp16 [n][k]. BM=BN=128, BK=32, 256 thr.
// AHEAD: A head-major [k/64][M][64] plane-stride lda. CHEAD: C fp16 head-major.
// C16: C fp16 row-major.
#define AST 20
template<bool BIAS, bool RES, bool RELU, bool AHEAD, bool CHEAD, bool C16>
__global__ void __launch_bounds__(256) hgemm_kernel(
    const __half* __restrict__ A, const __half* __restrict__ Bw,
    const float* __restrict__ bias, const float* __restrict__ res,
    void* __restrict__ C, int K, int lda, int ldc, size_t sB, size_t sC)
{
    __shared__ unsigned As[2][128*AST];
    __shared__ unsigned Bs[2][128*AST];
    const int tid = threadIdx.x, lane = tid & 31, wid = tid >> 5;
    const int g = lane >> 2, tg = lane & 3;
    const int bm = blockIdx.x * 128, bn = blockIdx.y * 128;
    const int z = blockIdx.z;
    const __half* Bz = Bw + (size_t)z * sB;
    const int KT = K >> 5;
    const int wm = (wid & 3) * 32, wn = (wid >> 2) * 64;

    const int r = tid >> 1, pp = tid & 1;
    uint4 pa[2], pb[2];

    auto loadAB = [&](int kt) {
        const __half* asrc = AHEAD
            ? A + (size_t)(kt >> 1) * lda + (size_t)(bm + r) * 64 + (kt & 1) * 32 + pp * 16
            : A + (size_t)(bm + r) * lda + kt * 32 + pp * 16;
        pa[0] = ((const uint4*)asrc)[0];
        pa[1] = ((const uint4*)asrc)[1];
        const uint4* bsrc = (const uint4*)(Bz + (size_t)(bn + r) * K + kt * 32 + pp * 16);
        pb[0] = bsrc[0];
        pb[1] = bsrc[1];
    };
    auto storeAB = [&](int buf) {
        *(uint4*)&As[buf][r*AST + pp*8]     = pa[0];
        *(uint4*)&As[buf][r*AST + pp*8 + 4] = pa[1];
        *(uint4*)&Bs[buf][r*AST + pp*8]     = pb[0];
        *(uint4*)&Bs[buf][r*AST + pp*8 + 4] = pb[1];
    };

    float acc[2][8][4] = {};

    loadAB(0); storeAB(0); __syncthreads();

    const uint32_t aBase = smem_u32(&As[0][0]);
    const uint32_t bBase = smem_u32(&Bs[0][0]);
    const int frA  = (wm + (lane & 15)) * AST + (lane >> 4) * 4;
    const int frB  = (wn + (lane & 15)) * AST + (lane >> 4) * 4;

    for (int kt = 0; kt < KT; kt++) {
        int buf = kt & 1;
        if (kt + 1 < KT) loadAB(kt + 1);
        uint32_t aT = aBase + buf * (128*AST*4);
        uint32_t bT = bBase + buf * (128*AST*4);
#pragma unroll
        for (int ks = 0; ks < 2; ks++) {
            int k0 = ks * 8;
            unsigned a0[4], a1[4], bb[8][2];
            LDSM4(a0, aT + (frA + k0) * 4);
            LDSM4(a1, aT + (frA + 16*AST + k0) * 4);
#pragma unroll
            for (int nj = 0; nj < 4; nj++) {
                unsigned t4[4];
                LDSM4(t4, bT + (frB + nj*16*AST + k0) * 4);
                bb[2*nj][0]   = t4[0]; bb[2*nj+1][0] = t4[1];
                bb[2*nj][1]   = t4[2]; bb[2*nj+1][1] = t4[3];
            }
#pragma unroll
            for (int ni = 0; ni < 8; ni++) {
                mma_f16(acc[0][ni], a0, bb[ni][0], bb[ni][1]);
                mma_f16(acc[1][ni], a1, bb[ni][0], bb[ni][1]);
            }
        }
        if (kt + 1 < KT) storeAB((kt + 1) & 1);
        __syncthreads();
    }

#pragma unroll
    for (int mi = 0; mi < 2; mi++) {
        int rr = bm + wm + mi*16 + g;
#pragma unroll
        for (int ni = 0; ni < 8; ni++) {
            int c = bn + wn + ni*8 + 2*tg;
            float2 v0 = make_float2(acc[mi][ni][0], acc[mi][ni][1]);
            float2 v1 = make_float2(acc[mi][ni][2], acc[mi][ni][3]);
            if (BIAS) {
                float2 bv = *(const float2*)(bias + c);
                v0.x += bv.x; v0.y += bv.y; v1.x += bv.x; v1.y += bv.y;
            }
            if (RES) {
                float2 r0v = *(const float2*)(res + (size_t)rr*ldc + c);
                float2 r1v = *(const float2*)(res + (size_t)(rr+8)*ldc + c);
                v0.x += r0v.x; v0.y += r0v.y; v1.x += r1v.x; v1.y += r1v.y;
            }
            if (RELU) {
                v0.x = fmaxf(v0.x, 0.f); v0.y = fmaxf(v0.y, 0.f);
                v1.x = fmaxf(v1.x, 0.f); v1.y = fmaxf(v1.y, 0.f);
            }
            if (CHEAD) {
                int plane = c >> 6, e = c & 63;
                __half* cp = (__half*)C + (size_t)z * sC
                           + (size_t)plane * HM_PLANE + (size_t)rr * 64 + e;
                *(__half2*)cp = __floats2half2_rn(v0.x, v0.y);
                *(__half2*)(cp + 8*64) = __floats2half2_rn(v1.x, v1.y);
            } else if (C16) {
                __half* cp = (__half*)C + (size_t)z * sC + (size_t)rr * ldc + c;
                *(__half2*)cp = __floats2half2_rn(v0.x, v0.y);
                *(__half2*)(cp + (size_t)8*ldc) = __floats2half2_rn(v1.x, v1.y);
            } else {
                float* cp = (float*)C + (size_t)z * sC + (size_t)rr * ldc + c;
                *(float2*)cp = v0;
                *(float2*)(cp + (size_t)8*ldc) = v1;
            }
        }
    }
}

// ---------------- fused scores + masked softmax; writes P fp32 (d_out) + fp16 mirror ----------
// grid (16,1,HB), 256 thr; 32 q-rows x full 512 s per block; scores stay in regs.
template<bool SELF>
__global__ void __launch_bounds__(256) scoresoftmax_kernel(
    const __half* __restrict__ Qroot, const __half* __restrict__ Kroot,
    const int* __restrict__ seq, float* __restrict__ Pout, __half* __restrict__ P16)
{
    __shared__ unsigned Qs[32*36];
    __shared__ unsigned Ks[128*36];
    __shared__ float maskv[512];
    __shared__ float red[256];

    const int tid = threadIdx.x, lane = tid & 31, wid = tid >> 5;
    const int g = lane >> 2, tg = lane & 3;
    const int wm = (wid & 1) * 16;        // 2 m groups
    const int wn = (wid >> 1) * 32;       // 4 n groups (chunk-local)
    const int q0 = blockIdx.x * 32;
    const int z = blockIdx.z, h = z >> 3, b = z & 7;

    const __half* Qb = Qroot + (size_t)h * HM_PLANE + (size_t)b * HM_Z + (size_t)q0 * DK;
    const __half* Kb = Kroot + (size_t)h * HM_PLANE + (size_t)b * HM_Z;

    if (tid < 64) {      // Q tile: 32 rows x 64 halves; 2 threads/row, 32 halves each
        int r = tid >> 1, part = tid & 1;
        const uint4* src = (const uint4*)(Qb + (size_t)r * DK + part * 32);
        int o = r*36 + part*16;
        *(uint4*)&Qs[o]      = src[0];
        *(uint4*)&Qs[o + 4]  = src[1];
        *(uint4*)&Qs[o + 8]  = src[2];
        *(uint4*)&Qs[o + 12] = src[3];
    }
    maskv[tid]       = (seq[b*LT + tid] == 0)       ? -INFINITY : 0.f;
    maskv[tid + 256] = (seq[b*LT + tid + 256] == 0) ? -INFINITY : 0.f;
    __syncthreads();

    const uint32_t qB = smem_u32(Qs);
    const uint32_t kB = smem_u32(Ks);

    const int ncomp = SELF ? ((blockIdx.x >> 2) + 1) : 4;

    float accS[4][4][4] = {};
    {
        const int frA = (wm + (lane & 15)) * 36 + (lane >> 4) * 4;
        const int frB = (wn + (lane & 15)) * 36 + (lane >> 4) * 4;
        for (int c = 0; c < ncomp; c++) {
            {   // K chunk: 128 rows x 64 halves
                int r = tid >> 1, part = tid & 1;
                const uint4* src = (const uint4*)(Kb + (size_t)(c*128 + r) * DK + part * 32);
                int o = r*36 + part*16;
                *(uint4*)&Ks[o]      = src[0];
                *(uint4*)&Ks[o + 4]  = src[1];
                *(uint4*)&Ks[o + 8]  = src[2];
                *(uint4*)&Ks[o + 12] = src[3];
            }
            __syncthreads();
#pragma unroll
            for (int ks = 0; ks < 4; ks++) {
                int k0 = ks * 8;
                unsigned a0[4], bb[4][2];
                LDSM4(a0, qB + (frA + k0) * 4);
#pragma unroll
                for (int nj = 0; nj < 2; nj++) {
                    unsigned t4[4];
                    LDSM4(t4, kB + (frB + nj*16*36 + k0) * 4);
                    bb[2*nj][0] = t4[0]; bb[2*nj+1][0] = t4[1];
                    bb[2*nj][1] = t4[2]; bb[2*nj+1][1] = t4[3];
                }
#pragma unroll
                for (int ni = 0; ni < 4; ni++)
                    mma_f16(accS[c][ni], a0, bb[ni][0], bb[ni][1]);
            }
            __syncthreads();
        }
    }

    // ---- masked softmax over registers ----
    const int row0 = q0 + wm + g;
    const int r0l = wm + g, r1l = wm + g + 8;
    float m0 = -INFINITY, m1 = -INFINITY;
#pragma unroll
    for (int c = 0; c < 4; c++)
#pragma unroll
        for (int ni = 0; ni < 4; ni++) {
            int col = c*128 + wn + ni*8 + tg*2;
            float* a = accS[c][ni];
            float mv0 = maskv[col], mv1 = maskv[col+1];
            a[0] = a[0]*ATT_SCALE + mv0;
            a[1] = a[1]*ATT_SCALE + mv1;
            a[2] = a[2]*ATT_SCALE + mv0;
            a[3] = a[3]*ATT_SCALE + mv1;
            if (SELF) {
                if (col     > row0)   a[0] = -INFINITY;
                if (col + 1 > row0)   a[1] = -INFINITY;
                if (col     > row0+8) a[2] = -INFINITY;
                if (col + 1 > row0+8) a[3] = -INFINITY;
            }
            m0 = fmaxf(m0, fmaxf(a[0], a[1]));
            m1 = fmaxf(m1, fmaxf(a[2], a[3]));
        }
    m0 = fmaxf(m0, __shfl_xor_sync(0xffffffffu, m0, 1));
    m0 = fmaxf(m0, __shfl_xor_sync(0xffffffffu, m0, 2));
    m1 = fmaxf(m1, __shfl_xor_sync(0xffffffffu, m1, 1));
    m1 = fmaxf(m1, __shfl_xor_sync(0xffffffffu, m1, 2));
    int wnidx = wid >> 1;
    if (tg == 0) { red[r0l*4 + wnidx] = m0; red[r1l*4 + wnidx] = m1; }
    __syncthreads();
    m0 = fmaxf(fmaxf(red[r0l*4], red[r0l*4+1]), fmaxf(red[r0l*4+2], red[r0l*4+3]));
    m1 = fmaxf(fmaxf(red[r1l*4], red[r1l*4+1]), fmaxf(red[r1l*4+2], red[r1l*4+3]));

    float s0 = 0.f, s1 = 0.f;
#pragma unroll
    for (int c = 0; c < 4; c++)
#pragma unroll
        for (int ni = 0; ni < 4; ni++) {
            float* a = accS[c][ni];
            a[0] = __expf(a[0] - m0); a[1] = __expf(a[1] - m0);
            a[2] = __expf(a[2] - m1); a[3] = __expf(a[3] - m1);
            s0 += a[0] + a[1];
            s1 += a[2] + a[3];
        }
    s0 += __shfl_xor_sync(0xffffffffu, s0, 1);
    s0 += __shfl_xor_sync(0xffffffffu, s0, 2);
    s1 += __shfl_xor_sync(0xffffffffu, s1, 1);
    s1 += __shfl_xor_sync(0xffffffffu, s1, 2);
    __syncthreads();
    if (tg == 0) { red[128 + r0l*4 + wnidx] = s0; red[128 + r1l*4 + wnidx] = s1; }
    __syncthreads();
    s0 = red[128+r0l*4] + red[128+r0l*4+1] + red[128+r0l*4+2] + red[128+r0l*4+3];
    s1 = red[128+r1l*4] + red[128+r1l*4+1] + red[128+r1l*4+2] + red[128+r1l*4+3];
    float inv0 = 1.f / s0, inv1 = 1.f / s1;

    // ---- write P fp32 + fp16 mirror ----
    float*  Prow0 = Pout + (size_t)z * LT * LT + (size_t)row0 * LT;
    float*  Prow1 = Prow0 + 8 * LT;
    __half* Hrow0 = P16 + (size_t)z * LT * LT + (size_t)row0 * LT;
    __half* Hrow1 = Hrow0 + 8 * LT;
#pragma unroll
    for (int c = 0; c < 4; c++)
#pragma unroll
        for (int ni = 0; ni < 4; ni++) {
            int col = c*128 + wn + ni*8 + tg*2;
            float* a = accS[c][ni];
            float p00 = a[0]*inv0, p01 = a[1]*inv0;
            float p10 = a[2]*inv1, p11 = a[3]*inv1;
            *(float2*)(Prow0 + col) = make_float2(p00, p01);
            *(float2*)(Prow1 + col) = make_float2(p10, p11);
            *(__half2*)(Hrow0 + col) = __floats2half2_rn(p00, p01);
            *(__half2*)(Hrow1 + col) = __floats2half2_rn(p10, p11);
        }
}

// ---------------- P @ V: P fp16, V fp16, out ao fp16 head-major ----------------
// grid (4,1,HB). BM=128 q, BN=64 e, BK=32 s, double-buffered. SELF: skip masked chunks.
template<bool SELF>
__global__ void __launch_bounds__(256) pv_kernel(
    const __half* __restrict__ P16, const __half* __restrict__ Vroot, __half* __restrict__ ao)
{
    __shared__ unsigned As[2][128*AST];
    __shared__ unsigned Bs[2][64*AST];
    const int tid = threadIdx.x, lane = tid & 31, wid = tid >> 5;
    const int g = lane >> 2, tg = lane & 3;
    const int wm = (wid & 3) * 32, wn = (wid >> 2) * 32;
    const int bm = blockIdx.x * 128;
    const int z = blockIdx.z, h = z >> 3, b = z & 7;

    const __half* Pz = P16 + (size_t)z * LT * LT;
    const __half* Vz = Vroot + (size_t)h * HM_PLANE + (size_t)b * HM_Z;

    const int r = tid >> 1, pp = tid & 1;
    const int vn = tid >> 2, kg = (tid & 3) * 4;
    uint4 pa[2];
    __half hv[8];

    auto loadAB = [&](int kt) {
        const uint4* asrc = (const uint4*)(Pz + (size_t)(bm + r) * LT + kt * 32 + pp * 16);
        pa[0] = asrc[0];
        pa[1] = asrc[1];
#pragma unroll
        for (int j = 0; j < 8; j++)
            hv[j] = Vz[(size_t)(kt*32 + kg*2 + j) * 64 + vn];
    };
    auto storeAB = [&](int buf) {
        *(uint4*)&As[buf][r*AST + pp*8]     = pa[0];
        *(uint4*)&As[buf][r*AST + pp*8 + 4] = pa[1];
        unsigned w0 = packhh(hv[0], hv[1]);
        unsigned w1 = packhh(hv[2], hv[3]);
        unsigned w2 = packhh(hv[4], hv[5]);
        unsigned w3 = packhh(hv[6], hv[7]);
        *(uint4*)&Bs[buf][vn*AST + kg] = make_uint4(w0, w1, w2, w3);
    };

    float acc[2][4][4] = {};

    loadAB(0); storeAB(0); __syncthreads();

    const uint32_t aBase = smem_u32(&As[0][0]);
    const uint32_t bBase = smem_u32(&Bs[0][0]);
    const int frA = (wm + (lane & 15)) * AST + (lane >> 4) * 4;
    const int frB = (wn + (lane & 15)) * AST + (lane >> 4) * 4;

    const int KT = SELF ? (blockIdx.x + 1) * 4 : 16;   // causal: s <= bm+127
    for (int kt = 0; kt < KT; kt++) {
        int buf = kt & 1;
        if (kt + 1 < KT) loadAB(kt + 1);
        uint32_t aT = aBase + buf * (128*AST*4);
        uint32_t bT = bBase + buf * (64*AST*4);
#pragma unroll
        for (int ks = 0; ks < 2; ks++) {
            int k0 = ks * 8;
            unsigned a0[4], a1[4], bb[4][2];
            LDSM4(a0, aT + (frA + k0) * 4);
            LDSM4(a1, aT + (frA + 16*AST + k0) * 4);
#pragma unroll
            for (int nj = 0; nj < 2; nj++) {
                unsigned t4[4];
                LDSM4(t4, bT + (frB + nj*16*AST + k0) * 4);
                bb[2*nj][0] = t4[0]; bb[2*nj+1][0] = t4[1];
                bb[2*nj][1] = t4[2]; bb[2*nj+1][1] = t4[3];
            }
#pragma unroll
            for (int ni = 0; ni < 4; ni++) {
                mma_f16(acc[0][ni], a0, bb[ni][0], bb[ni][1]);
                mma_f16(acc[1][ni], a1, bb[ni][0], bb[ni][1]);
            }
        }
        if (kt + 1 < KT) storeAB((kt + 1) & 1);
        __syncthreads();
    }

    __half* aoh = ao + (size_t)h * HM_PLANE;
#pragma unroll
    for (int mi = 0; mi < 2; mi++) {
        int rr = bm + wm + mi*16 + g;
        size_t tok = (size_t)b * LT + rr;
#pragma unroll
        for (int ni = 0; ni < 4; ni++) {
            int e = wn + ni*8 + 2*tg;
            *(__half2*)(aoh + tok*64 + e)     = __floats2half2_rn(acc[mi][ni][0], acc[mi][ni][1]);
            *(__half2*)(aoh + (tok+8)*64 + e) = __floats2half2_rn(acc[mi][ni][2], acc[mi][ni][3]);
        }
    }
}

// ---------------- LayerNorm (writes fp32 + fp16 mirror) ----------------
__global__ void ln_kernel(const float* __restrict__ in, const float* __restrict__ g,
                          const float* __restrict__ bb, float* __restrict__ out,
                          __half* __restrict__ out16)
{
    __shared__ float sh[4];
    int row = blockIdx.x;
    int tid = threadIdx.x;
    const float* r = in + (size_t)row*DM;
    float v[4];
    float s = 0.f;
#pragma unroll
    for (int i = 0; i < 4; i++) { v[i] = r[tid + i*128]; s += v[i]; }
#pragma unroll
    for (int o = 16; o > 0; o >>= 1) s += __shfl_xor_sync(0xffffffffu, s, o);
    if ((tid & 31) == 0) sh[tid >> 5] = s;
    __syncthreads();
    s = sh[0] + sh[1] + sh[2] + sh[3];
    float mu = s * (1.f / DM);
    float s2 = 0.f;
#pragma unroll
    for (int i = 0; i < 4; i++) { float d = v[i] - mu; s2 += d*d; }
#pragma unroll
    for (int o = 16; o > 0; o >>= 1) s2 += __shfl_xor_sync(0xffffffffu, s2, o);
    __syncthreads();
    if ((tid & 31) == 0) sh[tid >> 5] = s2;
    __syncthreads();
    s2 = sh[0] + sh[1] + sh[2] + sh[3];
    float inv = rsqrtf(s2 * (1.f / DM) + EPSLN);
#pragma unroll
    for (int i = 0; i < 4; i++) {
        int d = tid + i*128;
        float o = (v[i] - mu) * inv * g[d] + bb[d];
        out[(size_t)row*DM + d] = o;
        out16[(size_t)row*DM + d] = __float2half(o);
    }
}

// ---------------- host orchestration ----------------
extern "C" void kernel_launch(void* const* d_in, const int* in_sizes, int n_in,
                              void* d_out, int out_size)
{
    (void)in_sizes; (void)n_in; (void)out_size;
    const int*   tgt_seq = (const int*)  d_in[0];
    const int*   tgt_pos = (const int*)  d_in[1];
    const int*   src_seq = (const int*)  d_in[2];
    const float* enc_out = (const float*)d_in[3];
    const float* tgt_emb = (const float*)d_in[4];
    const float* pos_emb = (const float*)d_in[5];
    const float* slf_wq  = (const float*)d_in[6];
    const float* slf_wk  = (const float*)d_in[7];
    const float* slf_wv  = (const float*)d_in[8];
    const float* slf_pw  = (const float*)d_in[9];
    const float* slf_pb  = (const float*)d_in[10];
    const float* slf_g   = (const float*)d_in[11];
    const float* slf_b   = (const float*)d_in[12];
    const float* enc_wq  = (const float*)d_in[13];
    const float* enc_wk  = (const float*)d_in[14];
    const float* enc_wv  = (const float*)d_in[15];
    const float* enc_pw  = (const float*)d_in[16];
    const float* enc_pb  = (const float*)d_in[17];
    const float* enc_g   = (const float*)d_in[18];
    const float* enc_b   = (const float*)d_in[19];
    const float* ffn_w1  = (const float*)d_in[20];
    const float* ffn_b1  = (const float*)d_in[21];
    const float* ffn_w2  = (const float*)d_in[22];
    const float* ffn_b2  = (const float*)d_in[23];
    const float* ffn_g   = (const float*)d_in[24];
    const float* ffn_b   = (const float*)d_in[25];
    float* out = (float*)d_out;

    float *x, *tmp;
    __half *x16, *e16, *qkv, *kvc, *ao, *ffnb, *p16;
    __half *wqkvS, *wqC, *wkvC, *pwH, *f1H, *f2H;
    cudaGetSymbolAddress((void**)&x,     g_x);
    cudaGetSymbolAddress((void**)&x16,   g_x16);
    cudaGetSymbolAddress((void**)&e16,   g_e16);
    cudaGetSymbolAddress((void**)&tmp,   g_tmp);
    cudaGetSymbolAddress((void**)&qkv,   g_qkv);
    cudaGetSymbolAddress((void**)&kvc,   g_kvc);
    cudaGetSymbolAddress((void**)&ao,    g_ao);
    cudaGetSymbolAddress((void**)&ffnb,  g_ffn);
    cudaGetSymbolAddress((void**)&p16,   g_p16);
    cudaGetSymbolAddress((void**)&wqkvS, g_wqkvS);
    cudaGetSymbolAddress((void**)&wqC,   g_wqC);
    cudaGetSymbolAddress((void**)&wkvC,  g_wkvC);
    cudaGetSymbolAddress((void**)&pwH,   g_pwH);
    cudaGetSymbolAddress((void**)&f1H,   g_f1H);
    cudaGetSymbolAddress((void**)&f2H,   g_f2H);

    auto hProj = hgemm_kernel<false,false,false,false,true, true >;  // -> fp16 head-major
    auto hOut  = hgemm_kernel<true, true, false,true, false,false>;  // A head-major fp16, C fp32
    auto hF1   = hgemm_kernel<true, false,true, false,false,true >;  // C fp16 (ffnb)
    auto hF2   = hgemm_kernel<true, true, false,false,false,false>;  // C fp32

    dim3 tcb(32, 8);
    // merged qkv-type weight transpose (6 tensors, 1 launch)
    TCArgs ta;
    ta.src[0] = slf_wq; ta.dst[0] = wqkvS + (size_t)0*512*512;
    ta.src[1] = slf_wk; ta.dst[1] = wqkvS + (size_t)1*512*512;
    ta.src[2] = slf_wv; ta.dst[2] = wqkvS + (size_t)2*512*512;
    ta.src[3] = enc_wq; ta.dst[3] = wqC;
    ta.src[4] = enc_wk; ta.dst[4] = wkvC;
    ta.src[5] = enc_wv; ta.dst[5] = wkvC + (size_t)512*512;
    transconvQKV_kernel<<<dim3(16,2,288), tcb>>>(ta);
    transconv2_kernel<<<dim3(16,16,6), tcb>>>(slf_pw, pwH,                      512, 512, 1, (size_t)512*512, 0);
    transconv2_kernel<<<dim3(16,16,6), tcb>>>(enc_pw, pwH + (size_t)NL*512*512, 512, 512, 1, (size_t)512*512, 0);
    transconv2_kernel<<<dim3(16,64,6), tcb>>>(ffn_w1, f1H, 512, 2048, 1, (size_t)512*2048, 0);
    transconv2_kernel<<<dim3(64,16,6), tcb>>>(ffn_w2, f2H, 2048, 512, 1, (size_t)512*2048, 0);

    embed_kernel<<<(TOK*DM)/256, 256>>>(tgt_seq, tgt_pos, tgt_emb, pos_emb, x, x16);
    f2h_kernel<<<(TOK*DM)/256, 256>>>(enc_out, e16);

    // all layers' cross K/V at once
    hProj<<<dim3(32,8,6),256>>>(e16, wkvC, nullptr, nullptr, kvc,
                                512, 512, 0, (size_t)1024*512, (size_t)16*HM_PLANE);

    dim3 gSS(16, 1, HB);
    dim3 gPV(4, 1, HB);

    for (int l = 0; l < NL; l++) {
        size_t ld = (size_t)l * DM;
        const __half* kvl = kvc + (size_t)l * 16 * HM_PLANE;

        // ---- self attention ----
        hProj<<<dim3(32,12),256>>>(x16, wqkvS + (size_t)l*1536*512, nullptr, nullptr, qkv,
                                   512, 512, 0, 0, 0);
        float* slfA = out + X_SIZE + (size_t)l * ATT_L;
        scoresoftmax_kernel<true><<<gSS,256>>>(qkv, qkv + 8*HM_PLANE, tgt_seq, slfA, p16);
        pv_kernel<true><<<gPV,256>>>(p16, qkv + 16*HM_PLANE, ao);
        hOut<<<dim3(32,4),256>>>(ao, pwH + (size_t)l*512*512, slf_pb + ld, x, tmp,
                                 512, HM_PLANE, 512, 0, 0);
        ln_kernel<<<TOK,128>>>(tmp, slf_g + ld, slf_b + ld, x, x16);

        // ---- cross attention ----
        hProj<<<dim3(32,4),256>>>(x16, wqC + (size_t)l*512*512, nullptr, nullptr, qkv,
                                  512, 512, 0, 0, 0);
        float* encA = out + X_SIZE + SLF_SIZE + (size_t)l * ATT_L;
        scoresoftmax_kernel<false><<<gSS,256>>>(qkv, kvl, src_seq, encA, p16);
        pv_kernel<false><<<gPV,256>>>(p16, kvl + 8*HM_PLANE, ao);
        hOut<<<dim3(32,4),256>>>(ao, pwH + (size_t)(NL + l)*512*512, enc_pb + ld, x, tmp,
                                 512, HM_PLANE, 512, 0, 0);
        ln_kernel<<<TOK,128>>>(tmp, enc_g + ld, enc_b + ld, x, x16);

        // ---- FFN ----
        hF1<<<dim3(32,16),256>>>(x16, f1H + (size_t)l*512*2048, ffn_b1 + (size_t)l*DI, nullptr,
                                 ffnb, 512, 512, DI, 0, 0);
        hF2<<<dim3(32,4),256>>>(ffnb, f2H + (size_t)l*512*2048, ffn_b2 + ld, x, tmp,
                                2048, DI, 512, 0, 0);
        ln_kernel<<<TOK,128>>>(tmp, ffn_g + ld, ffn_b + ld, x, x16);
    }

    cudaMemcpyAsync(out, x, X_SIZE * sizeof(float), cudaMemcpyDeviceToDevice);
}

// round 13
// speedup vs baseline: 1.2998x; 1.1095x over previous
#include <cuda_runtime.h>
#include <cuda_fp16.h>
#include <cstdint>
#include <math.h>

// ---------------- problem constants ----------------
#define TB   8
#define LT   512
#define LS   512
#define DM   512
#define NH   8
#define DK   64
#define DV   64
#define DI   2048
#define NL   6
#define TOK  (TB*LT)   // 4096
#define HB   (NH*TB)   // 64

#define EPSLN 1e-5f
#define ATT_SCALE 0.044194173824159216f   // 1/sqrt(512)

#define X_SIZE   ((size_t)TOK*DM)
#define ATT_L    ((size_t)HB*LT*LT)
#define SLF_SIZE ((size_t)NL*ATT_L)

// head-major plane: [plane][tok][64]
#define HM_Z     ((size_t)LT*DK)          // 32768
#define HM_PLANE ((size_t)TOK*64)         // 262144

// ---------------- scratch ----------------
__device__ float  g_x   [TOK*DM];
__device__ __half g_x16 [TOK*DM];
__device__ __half g_e16 [TOK*DM];
__device__ float  g_tmp [TOK*DM];
__device__ __half g_qkv [24*TOK*64];           // self: q 0-7, k 8-15, v 16-23 (cross-Q reuses 0-7)
__device__ __half g_kvc [NL*16*TOK*64];        // cross K planes 0-7, V 8-15, per layer
__device__ __half g_ao  [8*TOK*64];
__device__ __half g_ffn [TOK*DI];
__device__ __half g_p16 [HB*LT*LT];            // fp16 mirror of current attention matrix

// fp16 weights, [n][k] layout
__device__ __half g_wqkvS[(size_t)NL*1536*512];
__device__ __half g_wqC  [(size_t)NL*512*512];
__device__ __half g_wkvC [(size_t)NL*1024*512];
__device__ __half g_pwH  [(size_t)2*NL*512*512];
__device__ __half g_f1H  [(size_t)NL*512*2048];
__device__ __half g_f2H  [(size_t)NL*512*2048];

// ---------------- helpers ----------------
__device__ __forceinline__ uint32_t smem_u32(const void* p) {
    uint32_t a;
    asm("{ .reg .u64 t; cvta.to.shared.u64 t, %1; cvt.u32.u64 %0, t; }" : "=r"(a) : "l"(p));
    return a;
}

#define LDSM4(r, addr) \
    asm volatile("ldmatrix.sync.aligned.m8n8.x4.shared.b16 {%0,%1,%2,%3}, [%4];" \
        : "=r"((r)[0]), "=r"((r)[1]), "=r"((r)[2]), "=r"((r)[3]) : "r"(addr))

#define LDSM4T(r, addr) \
    asm volatile("ldmatrix.sync.aligned.m8n8.x4.trans.shared.b16 {%0,%1,%2,%3}, [%4];" \
        : "=r"((r)[0]), "=r"((r)[1]), "=r"((r)[2]), "=r"((r)[3]) : "r"(addr))

#define CPA16(dst, src) \
    asm volatile("cp.async.cg.shared.global [%0], [%1], 16;" :: "r"(dst), "l"(src) : "memory")
#define CPA_COMMIT() asm volatile("cp.async.commit_group;" ::: "memory")
#define CPA_WAIT1()  asm volatile("cp.async.wait_group 1;" ::: "memory")
#define CPA_WAIT0()  asm volatile("cp.async.wait_group 0;" ::: "memory")

__device__ __forceinline__ void mma_f16(float* d, const unsigned* a, unsigned b0, unsigned b1)
{
    asm volatile("mma.sync.aligned.m16n8k16.row.col.f32.f16.f16.f32 "
        "{%0,%1,%2,%3}, {%4,%5,%6,%7}, {%8,%9}, {%0,%1,%2,%3};\n"
        : "+f"(d[0]), "+f"(d[1]), "+f"(d[2]), "+f"(d[3])
        : "r"(a[0]), "r"(a[1]), "r"(a[2]), "r"(a[3]), "r"(b0), "r"(b1));
}

__device__ __forceinline__ unsigned packh2(float e, float o)
{
    __half2 h = __floats2half2_rn(e, o);
    return *(unsigned*)&h;
}

// ---------------- embedding (fp32 + fp16 mirror) ----------------
__global__ void embed_kernel(const int* __restrict__ seq, const int* __restrict__ pos,
                             const float* __restrict__ emb, const float* __restrict__ pemb,
                             float* __restrict__ x, __half* __restrict__ x16)
{
    int i = blockIdx.x * 256 + threadIdx.x;
    int t = i / DM, d = i % DM;
    float v = emb[(size_t)seq[t]*DM + d] + pemb[(size_t)pos[t]*DM + d];
    x[i] = v;
    x16[i] = __float2half(v);
}

// ---------------- fp32 -> fp16 convert ----------------
__global__ void f2h_kernel(const float* __restrict__ in, __half* __restrict__ o)
{
    int i = blockIdx.x * 256 + threadIdx.x;
    o[i] = __float2half(in[i]);
}

// ---------------- transpose + fp16 convert: in[b][R][C] -> out[n=(h*C+c)][R] ----------------
__global__ void transconv2_kernel(const float* __restrict__ in, __half* __restrict__ outp,
                                  int R, int C, int nhb, size_t lplane, size_t nbase)
{
    __shared__ float t[32][33];
    int bidz = blockIdx.z;
    int l = bidz / nhb, h = bidz % nhb;
    int r0 = blockIdx.x * 32, c0 = blockIdx.y * 32;
    const float* ib = in + (size_t)bidz * R * C;
#pragma unroll
    for (int i = threadIdx.y; i < 32; i += 8)
        t[i][threadIdx.x] = ib[(size_t)(r0 + i) * C + c0 + threadIdx.x];
    __syncthreads();
    __half* ob = outp + (size_t)l * lplane + nbase;
#pragma unroll
    for (int i = threadIdx.y; i < 32; i += 8)
        ob[(size_t)(h * C + c0 + i) * R + r0 + threadIdx.x] = __float2half(t[threadIdx.x][i]);
}

// merged qkv-type transpose: six [NL*8][512][64] tensors in one launch
struct TCArgs {
    const float* src[6];
    __half*      dst[6];
};
__global__ void transconvQKV_kernel(TCArgs a)
{
    const size_t lp[6] = {(size_t)1536*512, (size_t)1536*512, (size_t)1536*512,
                          (size_t)512*512,  (size_t)1024*512, (size_t)1024*512};
    __shared__ float t[32][33];
    int zi = blockIdx.z;
    int w = zi / 48, bz = zi % 48;
    int l = bz / 8, h = bz % 8;
    int r0 = blockIdx.x * 32, c0 = blockIdx.y * 32;
    const float* ib = a.src[w] + (size_t)bz * 512 * 64;
#pragma unroll
    for (int i = threadIdx.y; i < 32; i += 8)
        t[i][threadIdx.x] = ib[(size_t)(r0 + i) * 64 + c0 + threadIdx.x];
    __syncthreads();
    __half* ob = a.dst[w] + (size_t)l * lp[w];
#pragma unroll
    for (int i = threadIdx.y; i < 32; i += 8)
        ob[(size_t)(h * 64 + c0 + i) * 512 + r0 + threadIdx.x] = __float2half(t[threadIdx.x][i]);
}

// ---------------- fp16 tensor-core GEMM, 3-stage cp.async pipeline ----------------
// A fp16, B fp16 [n][k]. BM=BN=128, BK=32, 256 thr, dynamic smem.
#define AST 20
#define HG_STAGE (128*AST)                 // uints per stage per operand
#define HG_SMEM  (3*2*HG_STAGE*4)          // 61440 bytes

template<bool BIAS, bool RES, bool RELU, bool AHEAD, bool CHEAD, bool C16>
__global__ void __launch_bounds__(256) hgemm_kernel(
    const __half* __restrict__ A, const __half* __restrict__ Bw,
    const float* __restrict__ bias, const float* __restrict__ res,
    void* __restrict__ C, int K, int lda, int ldc, size_t sB, size_t sC)
{
    extern __shared__ unsigned hsm[];
    unsigned* As = hsm;
    unsigned* Bs = hsm + 3*HG_STAGE;

    const int tid = threadIdx.x, lane = tid & 31, wid = tid >> 5;
    const int g = lane >> 2, tg = lane & 3;
    const int bm = blockIdx.x * 128, bn = blockIdx.y * 128;
    const int z = blockIdx.z;
    const __half* Bz = Bw + (size_t)z * sB;
    const int KT = K >> 5;
    const int wm = (wid & 3) * 32, wn = (wid >> 2) * 64;

    const int r = tid >> 1, pp = tid & 1;
    const uint32_t aBase = smem_u32(As);
    const uint32_t bBase = smem_u32(Bs);
    const uint32_t dA = aBase + (r*AST + pp*8)*4;
    const uint32_t dB = bBase + (r*AST + pp*8)*4;

    auto issue = [&](int buf, int kt) {
        const __half* asrc = AHEAD
            ? A + (size_t)(kt >> 1) * lda + (size_t)(bm + r) * 64 + (kt & 1) * 32 + pp * 16
            : A + (size_t)(bm + r) * lda + kt * 32 + pp * 16;
        uint32_t da = dA + buf * (HG_STAGE*4);
        CPA16(da, asrc);
        CPA16(da + 16, asrc + 8);
        const __half* bsrc = Bz + (size_t)(bn + r) * K + kt * 32 + pp * 16;
        uint32_t db = dB + buf * (HG_STAGE*4);
        CPA16(db, bsrc);
        CPA16(db + 16, bsrc + 8);
    };

    issue(0, 0); CPA_COMMIT();
    issue(1, 1); CPA_COMMIT();

    float acc[2][8][4] = {};
    const int frA  = (wm + (lane & 15)) * AST + (lane >> 4) * 4;
    const int frB  = (wn + (lane & 15)) * AST + (lane >> 4) * 4;

    for (int kt = 0; kt < KT; kt++) {
        if (kt + 1 < KT) { CPA_WAIT1(); } else { CPA_WAIT0(); }
        __syncthreads();
        int buf = kt % 3;
        uint32_t aT = aBase + buf * (HG_STAGE*4);
        uint32_t bT = bBase + buf * (HG_STAGE*4);
#pragma unroll
        for (int ks = 0; ks < 2; ks++) {
            int k0 = ks * 8;
            unsigned a0[4], a1[4], bb[8][2];
            LDSM4(a0, aT + (frA + k0) * 4);
            LDSM4(a1, aT + (frA + 16*AST + k0) * 4);
#pragma unroll
            for (int nj = 0; nj < 4; nj++) {
                unsigned t4[4];
                LDSM4(t4, bT + (frB + nj*16*AST + k0) * 4);
                bb[2*nj][0]   = t4[0]; bb[2*nj+1][0] = t4[1];
                bb[2*nj][1]   = t4[2]; bb[2*nj+1][1] = t4[3];
            }
#pragma unroll
            for (int ni = 0; ni < 8; ni++) {
                mma_f16(acc[0][ni], a0, bb[ni][0], bb[ni][1]);
                mma_f16(acc[1][ni], a1, bb[ni][0], bb[ni][1]);
            }
        }
        if (kt + 2 < KT) { issue((kt + 2) % 3, kt + 2); CPA_COMMIT(); }
    }

#pragma unroll
    for (int mi = 0; mi < 2; mi++) {
        int rr = bm + wm + mi*16 + g;
#pragma unroll
        for (int ni = 0; ni < 8; ni++) {
            int c = bn + wn + ni*8 + 2*tg;
            float2 v0 = make_float2(acc[mi][ni][0], acc[mi][ni][1]);
            float2 v1 = make_float2(acc[mi][ni][2], acc[mi][ni][3]);
            if (BIAS) {
                float2 bv = *(const float2*)(bias + c);
                v0.x += bv.x; v0.y += bv.y; v1.x += bv.x; v1.y += bv.y;
            }
            if (RES) {
                float2 r0v = *(const float2*)(res + (size_t)rr*ldc + c);
                float2 r1v = *(const float2*)(res + (size_t)(rr+8)*ldc + c);
                v0.x += r0v.x; v0.y += r0v.y; v1.x += r1v.x; v1.y += r1v.y;
            }
            if (RELU) {
                v0.x = fmaxf(v0.x, 0.f); v0.y = fmaxf(v0.y, 0.f);
                v1.x = fmaxf(v1.x, 0.f); v1.y = fmaxf(v1.y, 0.f);
            }
            if (CHEAD) {
                int plane = c >> 6, e = c & 63;
                __half* cp = (__half*)C + (size_t)z * sC
                           + (size_t)plane * HM_PLANE + (size_t)rr * 64 + e;
                *(__half2*)cp = __floats2half2_rn(v0.x, v0.y);
                *(__half2*)(cp + 8*64) = __floats2half2_rn(v1.x, v1.y);
            } else if (C16) {
                __half* cp = (__half*)C + (size_t)z * sC + (size_t)rr * ldc + c;
                *(__half2*)cp = __floats2half2_rn(v0.x, v0.y);
                *(__half2*)(cp + (size_t)8*ldc) = __floats2half2_rn(v1.x, v1.y);
            } else {
                float* cp = (float*)C + (size_t)z * sC + (size_t)rr * ldc + c;
                *(float2*)cp = v0;
                *(float2*)(cp + (size_t)8*ldc) = v1;
            }
        }
    }
}

// ---------------- fused scores + masked softmax; P fp32 (d_out) + fp16 mirror ----------
// grid (16,1,HB), 256 thr; 32 q-rows x full 512 s per block; scores stay in regs.
template<bool SELF>
__global__ void __launch_bounds__(256) scoresoftmax_kernel(
    const __half* __restrict__ Qroot, const __half* __restrict__ Kroot,
    const int* __restrict__ seq, float* __restrict__ Pout, __half* __restrict__ P16)
{
    __shared__ unsigned Qs[32*36];
    __shared__ unsigned Ks[128*36];
    __shared__ float maskv[512];
    __shared__ float red[256];

    const int tid = threadIdx.x, lane = tid & 31, wid = tid >> 5;
    const int g = lane >> 2, tg = lane & 3;
    const int wm = (wid & 1) * 16;
    const int wn = (wid >> 1) * 32;
    const int q0 = blockIdx.x * 32;
    const int z = blockIdx.z, h = z >> 3, b = z & 7;

    const __half* Qb = Qroot + (size_t)h * HM_PLANE + (size_t)b * HM_Z + (size_t)q0 * DK;
    const __half* Kb = Kroot + (size_t)h * HM_PLANE + (size_t)b * HM_Z;

    if (tid < 64) {
        int r = tid >> 1, part = tid & 1;
        const uint4* src = (const uint4*)(Qb + (size_t)r * DK + part * 32);
        int o = r*36 + part*16;
        *(uint4*)&Qs[o]      = src[0];
        *(uint4*)&Qs[o + 4]  = src[1];
        *(uint4*)&Qs[o + 8]  = src[2];
        *(uint4*)&Qs[o + 12] = src[3];
    }
    maskv[tid]       = (seq[b*LT + tid] == 0)       ? -INFINITY : 0.f;
    maskv[tid + 256] = (seq[b*LT + tid + 256] == 0) ? -INFINITY : 0.f;
    __syncthreads();

    const uint32_t qB = smem_u32(Qs);
    const uint32_t kB = smem_u32(Ks);

    const int ncomp = SELF ? ((blockIdx.x >> 2) + 1) : 4;

    float accS[4][4][4] = {};
    {
        const int frA = (wm + (lane & 15)) * 36 + (lane >> 4) * 4;
        const int frB = (wn + (lane & 15)) * 36 + (lane >> 4) * 4;
        for (int c = 0; c < ncomp; c++) {
            {
                int r = tid >> 1, part = tid & 1;
                const uint4* src = (const uint4*)(Kb + (size_t)(c*128 + r) * DK + part * 32);
                int o = r*36 + part*16;
                *(uint4*)&Ks[o]      = src[0];
                *(uint4*)&Ks[o + 4]  = src[1];
                *(uint4*)&Ks[o + 8]  = src[2];
                *(uint4*)&Ks[o + 12] = src[3];
            }
            __syncthreads();
#pragma unroll
            for (int ks = 0; ks < 4; ks++) {
                int k0 = ks * 8;
                unsigned a0[4], bb[4][2];
                LDSM4(a0, qB + (frA + k0) * 4);
#pragma unroll
                for (int nj = 0; nj < 2; nj++) {
                    unsigned t4[4];
                    LDSM4(t4, kB + (frB + nj*16*36 + k0) * 4);
                    bb[2*nj][0] = t4[0]; bb[2*nj+1][0] = t4[1];
                    bb[2*nj][1] = t4[2]; bb[2*nj+1][1] = t4[3];
                }
#pragma unroll
                for (int ni = 0; ni < 4; ni++)
                    mma_f16(accS[c][ni], a0, bb[ni][0], bb[ni][1]);
            }
            __syncthreads();
        }
    }

    const int row0 = q0 + wm + g;
    const int r0l = wm + g, r1l = wm + g + 8;
    float m0 = -INFINITY, m1 = -INFINITY;
#pragma unroll
    for (int c = 0; c < 4; c++)
#pragma unroll
        for (int ni = 0; ni < 4; ni++) {
            int col = c*128 + wn + ni*8 + tg*2;
            float* a = accS[c][ni];
            float mv0 = maskv[col], mv1 = maskv[col+1];
            a[0] = a[0]*ATT_SCALE + mv0;
            a[1] = a[1]*ATT_SCALE + mv1;
            a[2] = a[2]*ATT_SCALE + mv0;
            a[3] = a[3]*ATT_SCALE + mv1;
            if (SELF) {
                if (col     > row0)   a[0] = -INFINITY;
                if (col + 1 > row0)   a[1] = -INFINITY;
                if (col     > row0+8) a[2] = -INFINITY;
                if (col + 1 > row0+8) a[3] = -INFINITY;
            }
            m0 = fmaxf(m0, fmaxf(a[0], a[1]));
            m1 = fmaxf(m1, fmaxf(a[2], a[3]));
        }
    m0 = fmaxf(m0, __shfl_xor_sync(0xffffffffu, m0, 1));
    m0 = fmaxf(m0, __shfl_xor_sync(0xffffffffu, m0, 2));
    m1 = fmaxf(m1, __shfl_xor_sync(0xffffffffu, m1, 1));
    m1 = fmaxf(m1, __shfl_xor_sync(0xffffffffu, m1, 2));
    int wnidx = wid >> 1;
    if (tg == 0) { red[r0l*4 + wnidx] = m0; red[r1l*4 + wnidx] = m1; }
    __syncthreads();
    m0 = fmaxf(fmaxf(red[r0l*4], red[r0l*4+1]), fmaxf(red[r0l*4+2], red[r0l*4+3]));
    m1 = fmaxf(fmaxf(red[r1l*4], red[r1l*4+1]), fmaxf(red[r1l*4+2], red[r1l*4+3]));

    float s0 = 0.f, s1 = 0.f;
#pragma unroll
    for (int c = 0; c < 4; c++)
#pragma unroll
        for (int ni = 0; ni < 4; ni++) {
            float* a = accS[c][ni];
            a[0] = __expf(a[0] - m0); a[1] = __expf(a[1] - m0);
            a[2] = __expf(a[2] - m1); a[3] = __expf(a[3] - m1);
            s0 += a[0] + a[1];
            s1 += a[2] + a[3];
        }
    s0 += __shfl_xor_sync(0xffffffffu, s0, 1);
    s0 += __shfl_xor_sync(0xffffffffu, s0, 2);
    s1 += __shfl_xor_sync(0xffffffffu, s1, 1);
    s1 += __shfl_xor_sync(0xffffffffu, s1, 2);
    __syncthreads();
    if (tg == 0) { red[128 + r0l*4 + wnidx] = s0; red[128 + r1l*4 + wnidx] = s1; }
    __syncthreads();
    s0 = red[128+r0l*4] + red[128+r0l*4+1] + red[128+r0l*4+2] + red[128+r0l*4+3];
    s1 = red[128+r1l*4] + red[128+r1l*4+1] + red[128+r1l*4+2] + red[128+r1l*4+3];
    float inv0 = 1.f / s0, inv1 = 1.f / s1;

    float*  Prow0 = Pout + (size_t)z * LT * LT + (size_t)row0 * LT;
    float*  Prow1 = Prow0 + 8 * LT;
    __half* Hrow0 = P16 + (size_t)z * LT * LT + (size_t)row0 * LT;
    __half* Hrow1 = Hrow0 + 8 * LT;
#pragma unroll
    for (int c = 0; c < 4; c++)
#pragma unroll
        for (int ni = 0; ni < 4; ni++) {
            int col = c*128 + wn + ni*8 + tg*2;
            float* a = accS[c][ni];
            float p00 = a[0]*inv0, p01 = a[1]*inv0;
            float p10 = a[2]*inv1, p11 = a[3]*inv1;
            *(float2*)(Prow0 + col) = make_float2(p00, p01);
            *(float2*)(Prow1 + col) = make_float2(p10, p11);
            *(__half2*)(Hrow0 + col) = __floats2half2_rn(p00, p01);
            *(__half2*)(Hrow1 + col) = __floats2half2_rn(p10, p11);
        }
}

// ---------------- P @ V: cp.async 3-stage, V row-major + ldmatrix.trans ----------------
// grid (4,1,HB). BM=128 q, BN=64 e, BK=32 s. SELF: skip fully-masked chunks.
#define PVA_ST (128*AST)     // A stage uints
#define PVV_ST (32*36)       // V stage uints (32 s rows x 72 halves)
template<bool SELF>
__global__ void __launch_bounds__(256) pv_kernel(
    const __half* __restrict__ P16, const __half* __restrict__ Vroot, __half* __restrict__ ao)
{
    __shared__ unsigned Ap[3][PVA_ST];
    __shared__ unsigned Vst[3][PVV_ST];
    const int tid = threadIdx.x, lane = tid & 31, wid = tid >> 5;
    const int g = lane >> 2, tg = lane & 3;
    const int wm = (wid & 3) * 32, wn = (wid >> 2) * 32;
    const int bm = blockIdx.x * 128;
    const int z = blockIdx.z, h = z >> 3, b = z & 7;

    const __half* Pz = P16 + (size_t)z * LT * LT;
    const __half* Vz = Vroot + (size_t)h * HM_PLANE + (size_t)b * HM_Z;

    const int r = tid >> 1, pp = tid & 1;
    const int vrow = tid >> 3, vseg = tid & 7;
    const uint32_t aBase = smem_u32(&Ap[0][0]);
    const uint32_t vBase = smem_u32(&Vst[0][0]);
    const uint32_t dA = aBase + (r*AST + pp*8)*4;
    const uint32_t dV = vBase + (vrow*36 + vseg*4)*4;

    auto issue = [&](int buf, int kt) {
        const __half* asrc = Pz + (size_t)(bm + r) * LT + kt * 32 + pp * 16;
        uint32_t da = dA + buf * (PVA_ST*4);
        CPA16(da, asrc);
        CPA16(da + 16, asrc + 8);
        const __half* vsrc = Vz + (size_t)(kt*32 + vrow) * 64 + vseg * 8;
        CPA16(dV + buf * (PVV_ST*4), vsrc);
    };

    const int KT = SELF ? (blockIdx.x + 1) * 4 : 16;   // causal: s <= bm+127

    issue(0, 0); CPA_COMMIT();
    issue(1, 1); CPA_COMMIT();

    float acc[2][4][4] = {};
    const int frA = (wm + (lane & 15)) * AST + (lane >> 4) * 4;
    // trans-B lane addressing: row = k-in-16 pattern, col = n block
    const int vrow_l = (lane & 7) + ((lane >> 4) << 3);
    const int frBv = vrow_l*36 + (wn >> 1) + ((lane >> 3) & 1) * 4;

    for (int kt = 0; kt < KT; kt++) {
        if (kt + 1 < KT) { CPA_WAIT1(); } else { CPA_WAIT0(); }
        __syncthreads();
        int buf = kt % 3;
        uint32_t aT = aBase + buf * (PVA_ST*4);
        uint32_t vT = vBase + buf * (PVV_ST*4);
#pragma unroll
        for (int ks = 0; ks < 2; ks++) {
            unsigned a0[4], a1[4], bb[4][2];
            LDSM4(a0, aT + (frA + ks*8) * 4);
            LDSM4(a1, aT + (frA + 16*AST + ks*8) * 4);
#pragma unroll
            for (int nj = 0; nj < 2; nj++) {
                unsigned t4[4];
                LDSM4T(t4, vT + (frBv + ks*16*36 + nj*8) * 4);
                bb[2*nj][0] = t4[0]; bb[2*nj+1][0] = t4[1];
                bb[2*nj][1] = t4[2]; bb[2*nj+1][1] = t4[3];
            }
#pragma unroll
            for (int ni = 0; ni < 4; ni++) {
                mma_f16(acc[0][ni], a0, bb[ni][0], bb[ni][1]);
                mma_f16(acc[1][ni], a1, bb[ni][0], bb[ni][1]);
            }
        }
        if (kt + 2 < KT) { issue((kt + 2) % 3, kt + 2); CPA_COMMIT(); }
    }

    __half* aoh = ao + (size_t)h * HM_PLANE;
#pragma unroll
    for (int mi = 0; mi < 2; mi++) {
        int rr = bm + wm + mi*16 + g;
        size_t tok = (size_t)b * LT + rr;
#pragma unroll
        for (int ni = 0; ni < 4; ni++) {
            int e = wn + ni*8 + 2*tg;
            *(__half2*)(aoh + tok*64 + e)     = __floats2half2_rn(acc[mi][ni][0], acc[mi][ni][1]);
            *(__half2*)(aoh + (tok+8)*64 + e) = __floats2half2_rn(acc[mi][ni][2], acc[mi][ni][3]);
        }
    }
}

// ---------------- LayerNorm (writes fp32 + fp16 mirror) ----------------
__global__ void ln_kernel(const float* __restrict__ in, const float* __restrict__ g,
                          const float* __restrict__ bb, float* __restrict__ out,
                          __half* __restrict__ out16)
{
    __shared__ float sh[4];
    int row = blockIdx.x;
    int tid = threadIdx.x;
    const float* r = in + (size_t)row*DM;
    float v[4];
    float s = 0.f;
#pragma unroll
    for (int i = 0; i < 4; i++) { v[i] = r[tid + i*128]; s += v[i]; }
#pragma unroll
    for (int o = 16; o > 0; o >>= 1) s += __shfl_xor_sync(0xffffffffu, s, o);
    if ((tid & 31) == 0) sh[tid >> 5] = s;
    __syncthreads();
    s = sh[0] + sh[1] + sh[2] + sh[3];
    float mu = s * (1.f / DM);
    float s2 = 0.f;
#pragma unroll
    for (int i = 0; i < 4; i++) { float d = v[i] - mu; s2 += d*d; }
#pragma unroll
    for (int o = 16; o > 0; o >>= 1) s2 += __shfl_xor_sync(0xffffffffu, s2, o);
    __syncthreads();
    if ((tid & 31) == 0) sh[tid >> 5] = s2;
    __syncthreads();
    s2 = sh[0] + sh[1] + sh[2] + sh[3];
    float inv = rsqrtf(s2 * (1.f / DM) + EPSLN);
#pragma unroll
    for (int i = 0; i < 4; i++) {
        int d = tid + i*128;
        float o = (v[i] - mu) * inv * g[d] + bb[d];
        out[(size_t)row*DM + d] = o;
        out16[(size_t)row*DM + d] = __float2half(o);
    }
}

// ---------------- host orchestration ----------------
extern "C" void kernel_launch(void* const* d_in, const int* in_sizes, int n_in,
                              void* d_out, int out_size)
{
    (void)in_sizes; (void)n_in; (void)out_size;
    const int*   tgt_seq = (const int*)  d_in[0];
    const int*   tgt_pos = (const int*)  d_in[1];
    const int*   src_seq = (const int*)  d_in[2];
    const float* enc_out = (const float*)d_in[3];
    const float* tgt_emb = (const float*)d_in[4];
    const float* pos_emb = (const float*)d_in[5];
    const float* slf_wq  = (const float*)d_in[6];
    const float* slf_wk  = (const float*)d_in[7];
    const float* slf_wv  = (const float*)d_in[8];
    const float* slf_pw  = (const float*)d_in[9];
    const float* slf_pb  = (const float*)d_in[10];
    const float* slf_g   = (const float*)d_in[11];
    const float* slf_b   = (const float*)d_in[12];
    const float* enc_wq  = (const float*)d_in[13];
    const float* enc_wk  = (const float*)d_in[14];
    const float* enc_wv  = (const float*)d_in[15];
    const float* enc_pw  = (const float*)d_in[16];
    const float* enc_pb  = (const float*)d_in[17];
    const float* enc_g   = (const float*)d_in[18];
    const float* enc_b   = (const float*)d_in[19];
    const float* ffn_w1  = (const float*)d_in[20];
    const float* ffn_b1  = (const float*)d_in[21];
    const float* ffn_w2  = (const float*)d_in[22];
    const float* ffn_b2  = (const float*)d_in[23];
    const float* ffn_g   = (const float*)d_in[24];
    const float* ffn_b   = (const float*)d_in[25];
    float* out = (float*)d_out;

    float *x, *tmp;
    __half *x16, *e16, *qkv, *kvc, *ao, *ffnb, *p16;
    __half *wqkvS, *wqC, *wkvC, *pwH, *f1H, *f2H;
    cudaGetSymbolAddress((void**)&x,     g_x);
    cudaGetSymbolAddress((void**)&x16,   g_x16);
    cudaGetSymbolAddress((void**)&e16,   g_e16);
    cudaGetSymbolAddress((void**)&tmp,   g_tmp);
    cudaGetSymbolAddress((void**)&qkv,   g_qkv);
    cudaGetSymbolAddress((void**)&kvc,   g_kvc);
    cudaGetSymbolAddress((void**)&ao,    g_ao);
    cudaGetSymbolAddress((void**)&ffnb,  g_ffn);
    cudaGetSymbolAddress((void**)&p16,   g_p16);
    cudaGetSymbolAddress((void**)&wqkvS, g_wqkvS);
    cudaGetSymbolAddress((void**)&wqC,   g_wqC);
    cudaGetSymbolAddress((void**)&wkvC,  g_wkvC);
    cudaGetSymbolAddress((void**)&pwH,   g_pwH);
    cudaGetSymbolAddress((void**)&f1H,   g_f1H);
    cudaGetSymbolAddress((void**)&f2H,   g_f2H);

    auto hProj = hgemm_kernel<false,false,false,false,true, true >;  // -> fp16 head-major
    auto hOut  = hgemm_kernel<true, true, false,true, false,false>;  // A head-major fp16, C fp32
    auto hF1   = hgemm_kernel<true, false,true, false,false,true >;  // C fp16 (ffnb)
    auto hF2   = hgemm_kernel<true, true, false,false,false,false>;  // C fp32

    cudaFuncSetAttribute(hProj, cudaFuncAttributeMaxDynamicSharedMemorySize, HG_SMEM);
    cudaFuncSetAttribute(hOut,  cudaFuncAttributeMaxDynamicSharedMemorySize, HG_SMEM);
    cudaFuncSetAttribute(hF1,   cudaFuncAttributeMaxDynamicSharedMemorySize, HG_SMEM);
    cudaFuncSetAttribute(hF2,   cudaFuncAttributeMaxDynamicSharedMemorySize, HG_SMEM);

    dim3 tcb(32, 8);
    TCArgs ta;
    ta.src[0] = slf_wq; ta.dst[0] = wqkvS + (size_t)0*512*512;
    ta.src[1] = slf_wk; ta.dst[1] = wqkvS + (size_t)1*512*512;
    ta.src[2] = slf_wv; ta.dst[2] = wqkvS + (size_t)2*512*512;
    ta.src[3] = enc_wq; ta.dst[3] = wqC;
    ta.src[4] = enc_wk; ta.dst[4] = wkvC;
    ta.src[5] = enc_wv; ta.dst[5] = wkvC + (size_t)512*512;
    transconvQKV_kernel<<<dim3(16,2,288), tcb>>>(ta);
    transconv2_kernel<<<dim3(16,16,6), tcb>>>(slf_pw, pwH,                      512, 512, 1, (size_t)512*512, 0);
    transconv2_kernel<<<dim3(16,16,6), tcb>>>(enc_pw, pwH + (size_t)NL*512*512, 512, 512, 1, (size_t)512*512, 0);
    transconv2_kernel<<<dim3(16,64,6), tcb>>>(ffn_w1, f1H, 512, 2048, 1, (size_t)512*2048, 0);
    transconv2_kernel<<<dim3(64,16,6), tcb>>>(ffn_w2, f2H, 2048, 512, 1, (size_t)512*2048, 0);

    embed_kernel<<<(TOK*DM)/256, 256>>>(tgt_seq, tgt_pos, tgt_emb, pos_emb, x, x16);
    f2h_kernel<<<(TOK*DM)/256, 256>>>(enc_out, e16);

    // all layers' cross K/V at once
    hProj<<<dim3(32,8,6),256,HG_SMEM>>>(e16, wkvC, nullptr, nullptr, kvc,
                                        512, 512, 0, (size_t)1024*512, (size_t)16*HM_PLANE);

    dim3 gSS(16, 1, HB);
    dim3 gPV(4, 1, HB);

    for (int l = 0; l < NL; l++) {
        size_t ld = (size_t)l * DM;
        const __half* kvl = kvc + (size_t)l * 16 * HM_PLANE;

        // ---- self attention ----
        hProj<<<dim3(32,12),256,HG_SMEM>>>(x16, wqkvS + (size_t)l*1536*512, nullptr, nullptr, qkv,
                                           512, 512, 0, 0, 0);
        float* slfA = out + X_SIZE + (size_t)l * ATT_L;
        scoresoftmax_kernel<true><<<gSS,256>>>(qkv, qkv + 8*HM_PLANE, tgt_seq, slfA, p16);
        pv_kernel<true><<<gPV,256>>>(p16, qkv + 16*HM_PLANE, ao);
        hOut<<<dim3(32,4),256,HG_SMEM>>>(ao, pwH + (size_t)l*512*512, slf_pb + ld, x, tmp,
                                         512, HM_PLANE, 512, 0, 0);
        ln_kernel<<<TOK,128>>>(tmp, slf_g + ld, slf_b + ld, x, x16);

        // ---- cross attention ----
        hProj<<<dim3(32,4),256,HG_SMEM>>>(x16, wqC + (size_t)l*512*512, nullptr, nullptr, qkv,
                                          512, 512, 0, 0, 0);
        float* encA = out + X_SIZE + SLF_SIZE + (size_t)l * ATT_L;
        scoresoftmax_kernel<false><<<gSS,256>>>(qkv, kvl, src_seq, encA, p16);
        pv_kernel<false><<<gPV,256>>>(p16, kvl + 8*HM_PLANE, ao);
        hOut<<<dim3(32,4),256,HG_SMEM>>>(ao, pwH + (size_t)(NL + l)*512*512, enc_pb + ld, x, tmp,
                                         512, HM_PLANE, 512, 0, 0);
        ln_kernel<<<TOK,128>>>(tmp, enc_g + ld, enc_b + ld, x, x16);

        // ---- FFN ----
        hF1<<<dim3(32,16),256,HG_SMEM>>>(x16, f1H + (size_t)l*512*2048, ffn_b1 + (size_t)l*DI, nullptr,
                                         ffnb, 512, 512, DI, 0, 0);
        hF2<<<dim3(32,4),256,HG_SMEM>>>(ffnb, f2H + (size_t)l*512*2048, ffn_b2 + ld, x, tmp,
                                        2048, DI, 512, 0, 0);
        ln_kernel<<<TOK,128>>>(tmp, ffn_g + ld, ffn_b + ld, x, x16);
    }

    cudaMemcpyAsync(out, x, X_SIZE * sizeof(float), cudaMemcpyDeviceToDevice);
}